// round 15
// baseline (speedup 1.0000x reference)
#include <cuda_runtime.h>
#include <cuda_bf16.h>
#include <math.h>
#include <float.h>
#include <stdint.h>

#define B_N 8192
#define D_N 384
#define H_N 256
#define C_N 6
#define KMAX 16

// ---------------- scratch (static device globals; no runtime alloc) ----------
__device__ float         g_sq[B_N];
__device__ int           g_k[B_N];
__device__ float         g_h[(size_t)B_N * H_N];
__device__ int           g_topi[8 * (size_t)B_N * KMAX];   // candidate pool
__device__ int           g_idx[(size_t)B_N * KMAX];
__device__ __nv_bfloat16 g_xh[(size_t)B_N * D_N];          // bf16(x)

#define SWZ(o) ((o) ^ (((o) >> 3) & 0x70))

__device__ __forceinline__ uint32_t smem_addr_u32(const void* p) {
    uint32_t a;
    asm("{ .reg .u64 t; cvta.to.shared.u64 t, %1; cvt.u32.u64 %0, t; }"
        : "=r"(a) : "l"(p));
    return a;
}
__device__ __forceinline__ void cp16(uint32_t dst, const void* src) {
    asm volatile("cp.async.cg.shared.global [%0], [%1], 16;" :: "r"(dst), "l"(src));
}
__device__ __forceinline__ void ldsm4(uint32_t& r0, uint32_t& r1, uint32_t& r2,
                                     uint32_t& r3, uint32_t addr) {
    asm volatile("ldmatrix.sync.aligned.m8n8.x4.shared.b16 {%0,%1,%2,%3}, [%4];"
                 : "=r"(r0), "=r"(r1), "=r"(r2), "=r"(r3) : "r"(addr));
}
__device__ __forceinline__ void mma16816(float* c, const uint32_t* a,
                                         uint32_t b0, uint32_t b1) {
    asm volatile("mma.sync.aligned.m16n8k16.row.col.f32.bf16.bf16.f32 "
                 "{%0,%1,%2,%3}, {%4,%5,%6,%7}, {%8,%9}, {%0,%1,%2,%3};"
                 : "+f"(c[0]), "+f"(c[1]), "+f"(c[2]), "+f"(c[3])
                 : "r"(a[0]), "r"(a[1]), "r"(a[2]), "r"(a[3]),
                   "r"(b0), "r"(b1));
}
__device__ __forceinline__ void ins16(float* rv, unsigned short* rx, float kv,
                                      int col, float& cm) {
    int slot = 0;
    #pragma unroll
    for (int s = 1; s < 16; s++)
        if (rv[s] < rv[slot] || (rv[s] == rv[slot] && rx[s] > rx[slot])) slot = s;
    rv[slot] = kv; rx[slot] = (unsigned short)col;
    float nm = rv[0];
    #pragma unroll
    for (int s = 1; s < 16; s++) nm = fminf(nm, rv[s]);
    cm = nm;
}

// ---------------- K0: x -> bf16 ----------------------------------------------
__global__ void k_cvt(const float* __restrict__ x) {
    int row = blockIdx.x;
    int k   = threadIdx.x;                     // 384 threads
    g_xh[(size_t)row * D_N + k] = __float2bfloat16(x[(size_t)row * D_N + k]);
}

// ---------------- K1: sq[i] = ||x_i||^2 ; tau -> k ---------------------------
__global__ void k_sqtau(const float* __restrict__ x,
                        const float* __restrict__ Wtau,
                        const float* __restrict__ btau) {
    int row  = blockIdx.x * 8 + threadIdx.y;
    int lane = threadIdx.x;
    const float* xr = x + (size_t)row * D_N;
    float s = 0.f, t = 0.f;
    for (int i = lane; i < D_N; i += 32) {
        float v = xr[i];
        s = fmaf(v, v, s);
        t = fmaf(v, Wtau[i], t);
    }
    #pragma unroll
    for (int o = 16; o; o >>= 1) {
        s += __shfl_down_sync(0xffffffffu, s, o);
        t += __shfl_down_sync(0xffffffffu, t, o);
    }
    if (lane == 0) {
        g_sq[row] = s;
        float tau = 1.f / (1.f + expf(-(t + btau[0])));
        float kf  = rintf(16.f - 12.f * tau);
        kf = fminf(fmaxf(kf, 1.f), 16.f);
        g_k[row] = (int)kf;
    }
}

// ---------------- K2: h = relu(x @ W_proj + b_proj) --------------------------
__global__ __launch_bounds__(256) void k_proj(const float* __restrict__ x,
                                              const float* __restrict__ W,
                                              const float* __restrict__ bias) {
    __shared__ float As[16][68];
    __shared__ float Bs[16][68];
    int tid = threadIdx.x, tx = tid & 15, ty = tid >> 4;
    int mb = blockIdx.y * 64, nb = blockIdx.x * 64;
    float acc[4][4] = {};
    for (int kb = 0; kb < D_N; kb += 16) {
        {
            int r = tid >> 2, kq = (tid & 3) * 4;
            float4 va = *(const float4*)(x + (size_t)(mb + r) * D_N + kb + kq);
            As[kq + 0][r] = va.x; As[kq + 1][r] = va.y;
            As[kq + 2][r] = va.z; As[kq + 3][r] = va.w;
        }
        {
            int kr = tid >> 4, c = (tid & 15) * 4;
            float4 vb = *(const float4*)(W + (size_t)(kb + kr) * H_N + nb + c);
            *(float4*)&Bs[kr][c] = vb;
        }
        __syncthreads();
        #pragma unroll
        for (int k = 0; k < 16; k++) {
            float a[4], bv[4];
            #pragma unroll
            for (int i = 0; i < 4; i++) a[i] = As[k][ty * 4 + i];
            #pragma unroll
            for (int j = 0; j < 4; j++) bv[j] = Bs[k][tx * 4 + j];
            #pragma unroll
            for (int i = 0; i < 4; i++)
                #pragma unroll
                for (int j = 0; j < 4; j++)
                    acc[i][j] = fmaf(a[i], bv[j], acc[i][j]);
        }
        __syncthreads();
    }
    #pragma unroll
    for (int i = 0; i < 4; i++) {
        int row = mb + ty * 4 + i;
        #pragma unroll
        for (int j = 0; j < 4; j++) {
            int col = nb + tx * 4 + j;
            float v = acc[i][j] + bias[col];
            g_h[(size_t)row * H_N + col] = v > 0.f ? v : 0.f;
        }
    }
}

// ---------------- K3: barrier-free HMMA; A resident smem, B via LDG ----------
// grid (64 row-tiles, 2 col-halves); 1024 threads (8x4 warp grid); 1 CTA/SM
// SMEM: A resident 6x16KB | tv | ti | tmin   (NO pipeline, NO mainloop syncs)
#define NN_A_OFF    0
#define NN_TV_OFF   98304
#define NN_TI_OFF   (NN_TV_OFF + 512 * 16 * 4)       // 131072
#define NN_TMIN_OFF (NN_TI_OFF + 512 * 16 * 2)       // 147456
#define NN_SMEM     (NN_TMIN_OFF + 512 * 4)          // 149504
#define NN_TILES    32               // 4096 cols / 128
#define NN_KSTEPS   24               // 384 / 16

__global__ __launch_bounds__(1024, 1) void k_nn() {
    extern __shared__ __align__(1024) char smem[];
    uint32_t smem_u32 = smem_addr_u32(smem);
    float*          tv   = (float*)(smem + NN_TV_OFF);    // 512 lists x 16
    unsigned short* ti   = (unsigned short*)(smem + NN_TI_OFF);
    float*          tmin = (float*)(smem + NN_TMIN_OFF);  // 512

    int tid = threadIdx.x, lane = tid & 31, wid = tid >> 5;
    int mr = wid >> 2, nc = wid & 3;      // warp grid 8x4
    int mb = blockIdx.x * 128;
    int colbase = blockIdx.y * 4096;

    for (int i = tid; i < 512 * 16; i += 1024) { tv[i] = -FLT_MAX; ti[i] = 0xFFFF; }
    if (tid < 512) tmin[tid] = -FLT_MAX;

    int lrow = lane & 15, lkoff = (lane >> 4) * 16;
    int q4 = lane & 3;
    int r0 = mr * 16 + (lane >> 2);
    int r1 = r0 + 8;
    int l0 = r0 * 4 + nc, l1 = r1 * 4 + nc;

    // loop-invariant swizzled A-LDSM offsets (within one 16KB K-slab)
    uint32_t aoff[4];
    #pragma unroll
    for (int kk = 0; kk < 4; kk++)
        aoff[kk] = SWZ((uint32_t)((mr * 16 + lrow) * 128 + kk * 32 + lkoff));

    // prologue: load resident A once (6 K-slabs of 64 elems, SW128 rows)
    {
        int row = tid >> 3, j = tid & 7;
        uint32_t dsw = SWZ((uint32_t)(row * 128 + j * 16));
        #pragma unroll
        for (int s = 0; s < 6; s++)
            cp16(smem_u32 + NN_A_OFF + s * 16384 + dsw,
                 g_xh + (size_t)(mb + row) * D_N + s * 64 + j * 8);
    }
    asm volatile("cp.async.commit_group;" ::: "memory");
    asm volatile("cp.async.wait_group 0;" ::: "memory");
    __syncthreads();   // A + list init visible; LAST barrier until writeout

    // per-ni B pointers: lane supplies col c_i = nc*32 + ni*8 + (lane>>2),
    // element offset (lane&3)*2 within each 16-elem k-step group
    const unsigned* bp[4];
    #pragma unroll
    for (int ni = 0; ni < 4; ni++) {
        int c = colbase + nc * 32 + ni * 8 + (lane >> 2);
        bp[ni] = (const unsigned*)(g_xh + (size_t)c * D_N + q4 * 2);
    }
    const float2* sqp[4];
    #pragma unroll
    for (int ni = 0; ni < 4; ni++)
        sqp[ni] = (const float2*)(g_sq + colbase + nc * 32 + ni * 8 + 2 * q4);

    #pragma unroll 1
    for (int ct = 0; ct < NN_TILES; ct++) {
        float acc[4][4];
        #pragma unroll
        for (int ni = 0; ni < 4; ni++)
            #pragma unroll
            for (int q = 0; q < 4; q++) acc[ni][q] = 0.f;

        #pragma unroll 4
        for (int ks = 0; ks < NN_KSTEPS; ks++) {
            uint32_t af[4];
            ldsm4(af[0], af[1], af[2], af[3],
                  smem_u32 + NN_A_OFF + (ks >> 2) * 16384 + aoff[ks & 3]);
            // b0: k = 2*q4, 2*q4+1 ; b1: +8  (packed low/high = ldsm layout)
            unsigned b[4][2];
            #pragma unroll
            for (int ni = 0; ni < 4; ni++) {
                b[ni][0] = bp[ni][ks * 8];
                b[ni][1] = bp[ni][ks * 8 + 4];
            }
            #pragma unroll
            for (int ni = 0; ni < 4; ni++)
                mma16816(acc[ni], af, b[ni][0], b[ni][1]);
        }

        // ---- epilogue: approx keys vs own-list threshold; rare inserts ----
        float m0 = tmin[l0], m1 = tmin[l1];
        bool hit = false;
        #pragma unroll
        for (int ni = 0; ni < 4; ni++) {
            float2 s2 = *sqp[ni];
            float k0 = fmaf(2.f, acc[ni][0], -s2.x);
            float k1 = fmaf(2.f, acc[ni][1], -s2.y);
            float k2 = fmaf(2.f, acc[ni][2], -s2.x);
            float k3 = fmaf(2.f, acc[ni][3], -s2.y);
            hit |= (k0 > m0) | (k1 > m0) | (k2 > m1) | (k3 > m1);
        }
        unsigned mask = __ballot_sync(0xffffffffu, hit);
        if (mask) {
            #pragma unroll 1
            for (int phase = 0; phase < 4; phase++) {
                if (q4 == phase && hit) {
                    float cm0 = tmin[l0], cm1 = tmin[l1];
                    float* rv0 = tv + l0 * 16; unsigned short* rx0 = ti + l0 * 16;
                    float* rv1 = tv + l1 * 16; unsigned short* rx1 = ti + l1 * 16;
                    #pragma unroll 1
                    for (int ni = 0; ni < 4; ni++) {
                        float2 s2 = *sqp[ni];
                        float k0 = fmaf(2.f, acc[ni][0], -s2.x);
                        float k1 = fmaf(2.f, acc[ni][1], -s2.y);
                        float k2 = fmaf(2.f, acc[ni][2], -s2.x);
                        float k3 = fmaf(2.f, acc[ni][3], -s2.y);
                        int c0 = ct * 128 + nc * 32 + ni * 8 + 2 * q4;
                        if (k0 > cm0) ins16(rv0, rx0, k0, c0, cm0);
                        if (k1 > cm0) ins16(rv0, rx0, k1, c0 + 1, cm0);
                        if (k2 > cm1) ins16(rv1, rx1, k2, c0, cm1);
                        if (k3 > cm1) ins16(rv1, rx1, k3, c0 + 1, cm1);
                    }
                    tmin[l0] = cm0; tmin[l1] = cm1;
                }
                __syncwarp();
            }
        }

        // advance pointers to next 128 columns
        #pragma unroll
        for (int ni = 0; ni < 4; ni++) {
            bp[ni]  += 128 * (D_N / 2);
            sqp[ni] += 64;
        }
    }

    __syncthreads();

    // ---- dump candidate pool (exact pass re-ranks; no sort needed) ----
    if (tid < 512) {
        unsigned short* rx = ti + tid * 16;
        int row = mb + (tid >> 2);
        int l   = blockIdx.y * 4 + (tid & 3);      // 8 lists per row
        size_t base = ((size_t)l * B_N + row) * KMAX;
        #pragma unroll
        for (int s = 0; s < 16; s++)
            g_topi[base + s] = colbase + (int)rx[s];
    }
}

// ---------------- K3b: exact fp32 re-rank of the 128-candidate pool ----------
// one warp per row; static register indexing only; 4 candidates per iteration
__global__ __launch_bounds__(256) void k_exact(const float* __restrict__ x) {
    int lane = threadIdx.x & 31;
    int row  = (blockIdx.x * 256 + threadIdx.x) >> 5;

    const float4* xr4 = (const float4*)(x + (size_t)row * D_N);
    float4 xa[3];
    #pragma unroll
    for (int t2 = 0; t2 < 3; t2++) xa[t2] = xr4[lane + 32 * t2];

    int   cidx[4];
    float ckey[4];
    #pragma unroll
    for (int j = 0; j < 4; j++) {
        int p = lane * 4 + j;
        cidx[j] = g_topi[((size_t)(p >> 4) * B_N + row) * KMAX + (p & 15)];
    }

    #pragma unroll 1
    for (int p2 = 0; p2 < 32; p2++) {
        int c[4];
        #pragma unroll
        for (int j = 0; j < 4; j++) c[j] = __shfl_sync(0xffffffffu, cidx[j], p2);
        float d[4] = {0.f, 0.f, 0.f, 0.f};
        #pragma unroll
        for (int j = 0; j < 4; j++) {
            const float4* xc = (const float4*)(x + (size_t)c[j] * D_N);
            #pragma unroll
            for (int t2 = 0; t2 < 3; t2++) {
                float4 v = xc[lane + 32 * t2];
                d[j] = fmaf(xa[t2].x, v.x, d[j]);
                d[j] = fmaf(xa[t2].y, v.y, d[j]);
                d[j] = fmaf(xa[t2].z, v.z, d[j]);
                d[j] = fmaf(xa[t2].w, v.w, d[j]);
            }
        }
        #pragma unroll
        for (int o = 16; o; o >>= 1) {
            #pragma unroll
            for (int j = 0; j < 4; j++)
                d[j] += __shfl_xor_sync(0xffffffffu, d[j], o);
        }
        float k[4];
        #pragma unroll
        for (int j = 0; j < 4; j++) k[j] = fmaf(2.f, d[j], -g_sq[c[j]]);
        if (lane == p2) {
            #pragma unroll
            for (int j = 0; j < 4; j++) ckey[j] = k[j];
        }
    }

    int* out = g_idx + (size_t)row * KMAX;
    #pragma unroll 1
    for (int s = 0; s < KMAX; s++) {
        float bk = ckey[0]; int bi = cidx[0];
        #pragma unroll
        for (int j = 1; j < 4; j++) {
            if (ckey[j] > bk || (ckey[j] == bk && cidx[j] < bi)) {
                bk = ckey[j]; bi = cidx[j];
            }
        }
        #pragma unroll
        for (int o = 16; o; o >>= 1) {
            float ok = __shfl_xor_sync(0xffffffffu, bk, o);
            int   oi = __shfl_xor_sync(0xffffffffu, bi, o);
            if (ok > bk || (ok == bk && oi < bi)) { bk = ok; bi = oi; }
        }
        if (lane == 0) out[s] = bi;
        #pragma unroll
        for (int j = 0; j < 4; j++)
            if (cidx[j] == bi) ckey[j] = -FLT_MAX;
    }
}

// ---------------- K4: gather-mean -> W_res -> relu -> +h -> LN -> fc ---------
__global__ __launch_bounds__(256) void k_tail(const float* __restrict__ Wres,
                                              const float* __restrict__ bres,
                                              const float* __restrict__ lng,
                                              const float* __restrict__ lnb,
                                              const float* __restrict__ Wfc,
                                              const float* __restrict__ bfc,
                                              float* __restrict__ out) {
    extern __shared__ float sm[];
    float* agg  = sm;
    float* hs   = agg + 16 * H_N;
    float* Ws   = hs + 16 * H_N;
    int*   idxs = (int*)(Ws + 32 * H_N);
    int*   ks   = idxs + 16 * 16;

    int tid = threadIdx.x;
    int rb = blockIdx.x * 16;
    {
        int r = tid >> 4, j = tid & 15;
        idxs[tid] = g_idx[(size_t)(rb + r) * KMAX + j];
    }
    if (tid < 16) ks[tid] = g_k[rb + tid];
    __syncthreads();

    int c = tid;
    for (int r = 0; r < 16; r++) {
        int kr = ks[r];
        float s = 0.f;
        for (int j = 0; j < kr; j++)
            s += g_h[(size_t)idxs[r * 16 + j] * H_N + c];
        agg[r * H_N + c] = s / (float)kr;
        hs[r * H_N + c]  = g_h[(size_t)(rb + r) * H_N + c];
    }
    __syncthreads();

    float acc[16];
    #pragma unroll
    for (int r = 0; r < 16; r++) acc[r] = 0.f;
    for (int kb = 0; kb < H_N; kb += 32) {
        __syncthreads();
        for (int kk = 0; kk < 32; kk++)
            Ws[kk * H_N + c] = Wres[(size_t)(kb + kk) * H_N + c];
        __syncthreads();
        for (int kk = 0; kk < 32; kk++) {
            float w = Ws[kk * H_N + c];
            #pragma unroll
            for (int r = 0; r < 16; r++)
                acc[r] = fmaf(agg[r * H_N + kb + kk], w, acc[r]);
        }
    }
    __syncthreads();

    float brc = bres[c];
    for (int r = 0; r < 16; r++) {
        float rv = acc[r] + brc;
        rv = rv > 0.f ? rv : 0.f;
        agg[r * H_N + c] = hs[r * H_N + c] + rv;
    }
    __syncthreads();

    int lane = tid & 31, wid = tid >> 5;
    for (int rr = 0; rr < 2; rr++) {
        int r = wid * 2 + rr;
        int row = rb + r;
        float* z = agg + r * H_N;
        float s = 0.f;
        #pragma unroll
        for (int t = 0; t < 8; t++) s += z[lane + 32 * t];
        #pragma unroll
        for (int o = 16; o; o >>= 1) s += __shfl_xor_sync(0xffffffffu, s, o);
        float mu = s * (1.f / 256.f);
        float vs = 0.f;
        #pragma unroll
        for (int t = 0; t < 8; t++) {
            float d = z[lane + 32 * t] - mu;
            vs = fmaf(d, d, vs);
        }
        #pragma unroll
        for (int o = 16; o; o >>= 1) vs += __shfl_xor_sync(0xffffffffu, vs, o);
        float rstd = rsqrtf(vs * (1.f / 256.f) + 1e-5f);

        float vals[8];
        #pragma unroll
        for (int t = 0; t < 8; t++) {
            int col = lane + 32 * t;
            float zn = (z[col] - mu) * rstd;
            vals[t] = zn * lng[col] + lnb[col];
        }
        #pragma unroll
        for (int cc = 0; cc < C_N; cc++) {
            float p = 0.f;
            #pragma unroll
            for (int t = 0; t < 8; t++) {
                int col = lane + 32 * t;
                p = fmaf(vals[t], Wfc[(size_t)col * C_N + cc], p);
            }
            #pragma unroll
            for (int o = 16; o; o >>= 1) p += __shfl_xor_sync(0xffffffffu, p, o);
            if (lane == 0) out[(size_t)row * C_N + cc] = p + bfc[cc];
        }
    }
}

// ---------------- launch ------------------------------------------------------
extern "C" void kernel_launch(void* const* d_in, const int* in_sizes, int n_in,
                              void* d_out, int out_size) {
    const float* x  = (const float*)d_in[0];
    const float* Wp = (const float*)d_in[1];
    const float* bp = (const float*)d_in[2];
    const float* Wt = (const float*)d_in[3];
    const float* bt = (const float*)d_in[4];
    const float* Wr = (const float*)d_in[5];
    const float* br = (const float*)d_in[6];
    const float* lg = (const float*)d_in[7];
    const float* lb = (const float*)d_in[8];
    const float* Wf = (const float*)d_in[9];
    const float* bf = (const float*)d_in[10];
    float* out = (float*)d_out;

    const int SMEM_TAIL = (16 * 256 * 2 + 32 * 256 + 16 * 16 + 16) * 4;
    cudaFuncSetAttribute(k_tail, cudaFuncAttributeMaxDynamicSharedMemorySize, SMEM_TAIL);
    cudaFuncSetAttribute(k_nn,   cudaFuncAttributeMaxDynamicSharedMemorySize, NN_SMEM);

    k_cvt<<<B_N, D_N>>>(x);
    k_sqtau<<<B_N / 8, dim3(32, 8)>>>(x, Wt, bt);
    k_proj<<<dim3(H_N / 64, B_N / 64), 256>>>(x, Wp, bp);
    k_nn<<<dim3(B_N / 128, 2), 1024, NN_SMEM>>>();
    k_exact<<<B_N / 8, 256>>>(x);
    k_tail<<<B_N / 16, 256, SMEM_TAIL>>>(Wr, br, lg, lb, Wf, bf, out);
}

// round 16
// speedup vs baseline: 1.2700x; 1.2700x over previous
#include <cuda_runtime.h>
#include <cuda_bf16.h>
#include <math.h>
#include <float.h>
#include <stdint.h>

#define B_N 8192
#define D_N 384
#define H_N 256
#define C_N 6
#define KMAX 16
#define NPART 4            // column quarters; x2 nc sub-lists -> 8 lists/row

// ---------------- scratch (static device globals; no runtime alloc) ----------
__device__ float         g_sq[B_N];
__device__ int           g_k[B_N];
__device__ float         g_h[(size_t)B_N * H_N];
__device__ float         g_topv[8 * (size_t)B_N * KMAX];   // approx keys
__device__ int           g_topi[8 * (size_t)B_N * KMAX];   // candidate pool
__device__ int           g_idx[(size_t)B_N * KMAX];
__device__ __nv_bfloat16 g_xh[(size_t)B_N * D_N];          // bf16(x)

#define SWZ(o) ((o) ^ (((o) >> 3) & 0x70))

__device__ __forceinline__ uint32_t smem_addr_u32(const void* p) {
    uint32_t a;
    asm("{ .reg .u64 t; cvta.to.shared.u64 t, %1; cvt.u32.u64 %0, t; }"
        : "=r"(a) : "l"(p));
    return a;
}
__device__ __forceinline__ void cp16(uint32_t dst, const void* src) {
    asm volatile("cp.async.cg.shared.global [%0], [%1], 16;" :: "r"(dst), "l"(src));
}
__device__ __forceinline__ void cp_commit() {
    asm volatile("cp.async.commit_group;" ::: "memory");
}
__device__ __forceinline__ void ldsm4(uint32_t& r0, uint32_t& r1, uint32_t& r2,
                                     uint32_t& r3, uint32_t addr) {
    asm volatile("ldmatrix.sync.aligned.m8n8.x4.shared.b16 {%0,%1,%2,%3}, [%4];"
                 : "=r"(r0), "=r"(r1), "=r"(r2), "=r"(r3) : "r"(addr));
}
__device__ __forceinline__ void mma16816(float* c, const uint32_t* a,
                                         uint32_t b0, uint32_t b1) {
    asm volatile("mma.sync.aligned.m16n8k16.row.col.f32.bf16.bf16.f32 "
                 "{%0,%1,%2,%3}, {%4,%5,%6,%7}, {%8,%9}, {%0,%1,%2,%3};"
                 : "+f"(c[0]), "+f"(c[1]), "+f"(c[2]), "+f"(c[3])
                 : "r"(a[0]), "r"(a[1]), "r"(a[2]), "r"(a[3]),
                   "r"(b0), "r"(b1));
}
__device__ __forceinline__ void ins16(float* rv, unsigned short* rx, float kv,
                                      int col, float& cm) {
    int slot = 0;
    #pragma unroll
    for (int s = 1; s < 16; s++)
        if (rv[s] < rv[slot] || (rv[s] == rv[slot] && rx[s] > rx[slot])) slot = s;
    rv[slot] = kv; rx[slot] = (unsigned short)col;
    float nm = rv[0];
    #pragma unroll
    for (int s = 1; s < 16; s++) nm = fminf(nm, rv[s]);
    cm = nm;
}

// ---------------- K0: x -> bf16 ----------------------------------------------
__global__ void k_cvt(const float* __restrict__ x) {
    int row = blockIdx.x;
    int k   = threadIdx.x;                     // 384 threads
    g_xh[(size_t)row * D_N + k] = __float2bfloat16(x[(size_t)row * D_N + k]);
}

// ---------------- K1: sq[i] = ||x_i||^2 ; tau -> k ---------------------------
__global__ void k_sqtau(const float* __restrict__ x,
                        const float* __restrict__ Wtau,
                        const float* __restrict__ btau) {
    int row  = blockIdx.x * 8 + threadIdx.y;
    int lane = threadIdx.x;
    const float* xr = x + (size_t)row * D_N;
    float s = 0.f, t = 0.f;
    for (int i = lane; i < D_N; i += 32) {
        float v = xr[i];
        s = fmaf(v, v, s);
        t = fmaf(v, Wtau[i], t);
    }
    #pragma unroll
    for (int o = 16; o; o >>= 1) {
        s += __shfl_down_sync(0xffffffffu, s, o);
        t += __shfl_down_sync(0xffffffffu, t, o);
    }
    if (lane == 0) {
        g_sq[row] = s;
        float tau = 1.f / (1.f + expf(-(t + btau[0])));
        float kf  = rintf(16.f - 12.f * tau);
        kf = fminf(fmaxf(kf, 1.f), 16.f);
        g_k[row] = (int)kf;
    }
}

// ---------------- K2: h = relu(x @ W_proj + b_proj) --------------------------
__global__ __launch_bounds__(256) void k_proj(const float* __restrict__ x,
                                              const float* __restrict__ W,
                                              const float* __restrict__ bias) {
    __shared__ float As[16][68];
    __shared__ float Bs[16][68];
    int tid = threadIdx.x, tx = tid & 15, ty = tid >> 4;
    int mb = blockIdx.y * 64, nb = blockIdx.x * 64;
    float acc[4][4] = {};
    for (int kb = 0; kb < D_N; kb += 16) {
        {
            int r = tid >> 2, kq = (tid & 3) * 4;
            float4 va = *(const float4*)(x + (size_t)(mb + r) * D_N + kb + kq);
            As[kq + 0][r] = va.x; As[kq + 1][r] = va.y;
            As[kq + 2][r] = va.z; As[kq + 3][r] = va.w;
        }
        {
            int kr = tid >> 4, c = (tid & 15) * 4;
            float4 vb = *(const float4*)(W + (size_t)(kb + kr) * H_N + nb + c);
            *(float4*)&Bs[kr][c] = vb;
        }
        __syncthreads();
        #pragma unroll
        for (int k = 0; k < 16; k++) {
            float a[4], bv[4];
            #pragma unroll
            for (int i = 0; i < 4; i++) a[i] = As[k][ty * 4 + i];
            #pragma unroll
            for (int j = 0; j < 4; j++) bv[j] = Bs[k][tx * 4 + j];
            #pragma unroll
            for (int i = 0; i < 4; i++)
                #pragma unroll
                for (int j = 0; j < 4; j++)
                    acc[i][j] = fmaf(a[i], bv[j], acc[i][j]);
        }
        __syncthreads();
    }
    #pragma unroll
    for (int i = 0; i < 4; i++) {
        int row = mb + ty * 4 + i;
        #pragma unroll
        for (int j = 0; j < 4; j++) {
            int col = nb + tx * 4 + j;
            float v = acc[i][j] + bias[col];
            g_h[(size_t)row * H_N + col] = v > 0.f ? v : 0.f;
        }
    }
}

// ---------------- K3: single-term bf16 HMMA, unified 192-slab stream ---------
// grid (64 row-tiles, 4 col-quarters); 512 threads (8x2 warp grid); 2 CTA/SM
#define NN_STAGE    24576
#define NN_BOFF     16384
#define NN_TV_OFF   (3 * NN_STAGE)                   // 73728
#define NN_TI_OFF   (NN_TV_OFF + 256 * 16 * 4)       // 90112
#define NN_TMIN_OFF (NN_TI_OFF + 256 * 16 * 2)       // 98304
#define NN_SQC_OFF  (NN_TMIN_OFF + 256 * 4)          // 99328
#define NN_SMEM     (NN_SQC_OFF + 2 * 64 * 4)        // 99840
#define NN_TILES    (2048 / 64)      // 32 col tiles per quarter
#define NN_SLABS    6                // 384 / 64
#define NN_GTOT     (NN_TILES * NN_SLABS)            // 192

__device__ __forceinline__ void load_slab(uint32_t smem_u32, int stage,
                                          int mb, int cb, int t, int tid) {
    uint32_t sbase = smem_u32 + stage * NN_STAGE;
    // A: 128 rows x 128B = 1024 chunks of 16B; 2 per thread
    #pragma unroll
    for (int i = 0; i < 2; i++) {
        int c = tid + i * 512;
        int row = c >> 3, j = c & 7;
        uint32_t dst = SWZ((uint32_t)(row * 128 + j * 16));
        cp16(sbase + dst, g_xh + (size_t)(mb + row) * D_N + t * 64 + j * 8);
    }
    // B: 64 rows x 128B = 512 chunks; 1 per thread
    {
        int c = tid;
        int row = c >> 3, j = c & 7;
        uint32_t dst = SWZ((uint32_t)(row * 128 + j * 16));
        cp16(sbase + NN_BOFF + dst, g_xh + (size_t)(cb + row) * D_N + t * 64 + j * 8);
    }
    cp_commit();
}

__global__ __launch_bounds__(512, 2) void k_nn() {
    extern __shared__ __align__(1024) char smem[];
    uint32_t smem_u32 = smem_addr_u32(smem);
    float*          tv   = (float*)(smem + NN_TV_OFF);    // 256 lists x 16
    unsigned short* ti   = (unsigned short*)(smem + NN_TI_OFF);
    float*          tmin = (float*)(smem + NN_TMIN_OFF);  // 256
    float*          sqc  = (float*)(smem + NN_SQC_OFF);   // [2][64]

    int tid = threadIdx.x, lane = tid & 31, wid = tid >> 5;
    int mr = wid >> 1, nc = wid & 1;      // warp grid 8x2
    int mb = blockIdx.x * 128;
    int colbase = blockIdx.y * 2048;

    for (int i = tid; i < 256 * 16; i += 512) { tv[i] = -FLT_MAX; ti[i] = 0xFFFF; }
    if (tid < 256) tmin[tid] = -FLT_MAX;

    int lrow = lane & 15, lkoff = (lane >> 4) * 16;
    int q4 = lane & 3;
    int r0 = mr * 16 + (lane >> 2);
    int r1 = r0 + 8;
    int l0 = r0 * 2 + nc, l1 = r1 * 2 + nc;

    // prologue: global slabs 0,1 (tile 0 slabs 0,1) + sq tile 0
    load_slab(smem_u32, 0, mb, colbase, 0, tid);
    load_slab(smem_u32, 1, mb, colbase, 1, tid);
    if (tid < 64) sqc[tid] = g_sq[colbase + tid];

    float acc[4][4];
    #pragma unroll
    for (int ni = 0; ni < 4; ni++)
        #pragma unroll
        for (int q = 0; q < 4; q++) acc[ni][q] = 0.f;

    int ct = 0, sidx = 0;
    #pragma unroll 1
    for (int g = 0; g < NN_GTOT; g++) {
        if (g == NN_GTOT - 1)
            asm volatile("cp.async.wait_group 0;" ::: "memory");
        else
            asm volatile("cp.async.wait_group 1;" ::: "memory");
        __syncthreads();

        // issue slab g+2 (crosses tile boundaries — no drain between tiles)
        if (g + 2 < NN_GTOT) {
            int gn = g + 2;
            int tn = gn / NN_SLABS, sn = gn - tn * NN_SLABS;
            load_slab(smem_u32, gn % 3, mb, colbase + tn * 64, sn, tid);
        }
        // prefetch next tile's sq two slabs before its epilogue is needed
        if (sidx == 4 && ct + 1 < NN_TILES && tid < 64)
            sqc[((ct + 1) & 1) * 64 + tid] = g_sq[colbase + (ct + 1) * 64 + tid];

        uint32_t sbase = smem_u32 + (g % 3) * NN_STAGE;
        uint32_t aBase = sbase;
        uint32_t bBase = sbase + NN_BOFF;

        #pragma unroll
        for (int kk = 0; kk < 4; kk++) {
            uint32_t af[4];
            {
                int row = mr * 16 + lrow;
                uint32_t off = SWZ((uint32_t)(row * 128 + kk * 32 + lkoff));
                ldsm4(af[0], af[1], af[2], af[3], aBase + off);
            }
            #pragma unroll
            for (int bi = 0; bi < 2; bi++) {
                int row = nc * 32 + bi * 16 + lrow;
                uint32_t off = SWZ((uint32_t)(row * 128 + kk * 32 + lkoff));
                uint32_t b0, b1, b2, b3;
                ldsm4(b0, b1, b2, b3, bBase + off);
                mma16816(acc[bi * 2 + 0], af, b0, b2);
                mma16816(acc[bi * 2 + 1], af, b1, b3);
            }
        }

        if (sidx == NN_SLABS - 1) {
            // ---- epilogue for tile ct: approx keys + rare inserts ----
            const float* sqp = sqc + (ct & 1) * 64;
            float m0 = tmin[l0], m1 = tmin[l1];
            bool hit = false;
            #pragma unroll
            for (int ni = 0; ni < 4; ni++) {
                int c0 = nc * 32 + ni * 8 + 2 * q4;
                float s0 = sqp[c0], s1 = sqp[c0 + 1];
                float k0 = fmaf(2.f, acc[ni][0], -s0);
                float k1 = fmaf(2.f, acc[ni][1], -s1);
                float k2 = fmaf(2.f, acc[ni][2], -s0);
                float k3 = fmaf(2.f, acc[ni][3], -s1);
                hit |= (k0 > m0) | (k1 > m0) | (k2 > m1) | (k3 > m1);
            }
            unsigned mask = __ballot_sync(0xffffffffu, hit);
            if (mask) {
                #pragma unroll 1
                for (int phase = 0; phase < 4; phase++) {
                    if (q4 == phase && hit) {
                        float cm0 = tmin[l0], cm1 = tmin[l1];
                        float* rv0 = tv + l0 * 16; unsigned short* rx0 = ti + l0 * 16;
                        float* rv1 = tv + l1 * 16; unsigned short* rx1 = ti + l1 * 16;
                        #pragma unroll 1
                        for (int ni = 0; ni < 4; ni++) {
                            int cl = nc * 32 + ni * 8 + 2 * q4;
                            float s0 = sqp[cl], s1 = sqp[cl + 1];
                            float k0 = fmaf(2.f, acc[ni][0], -s0);
                            float k1 = fmaf(2.f, acc[ni][1], -s1);
                            float k2 = fmaf(2.f, acc[ni][2], -s0);
                            float k3 = fmaf(2.f, acc[ni][3], -s1);
                            int c0 = ct * 64 + cl;
                            if (k0 > cm0) ins16(rv0, rx0, k0, c0, cm0);
                            if (k1 > cm0) ins16(rv0, rx0, k1, c0 + 1, cm0);
                            if (k2 > cm1) ins16(rv1, rx1, k2, c0, cm1);
                            if (k3 > cm1) ins16(rv1, rx1, k3, c0 + 1, cm1);
                        }
                        tmin[l0] = cm0; tmin[l1] = cm1;
                    }
                    __syncwarp();
                }
            }
            #pragma unroll
            for (int ni = 0; ni < 4; ni++)
                #pragma unroll
                for (int q = 0; q < 4; q++) acc[ni][q] = 0.f;
            ct++; sidx = 0;
        } else {
            sidx++;
        }
    }

    __syncthreads();

    // ---- dump candidate pool + approx keys (exact pass prefilters+re-ranks) ----
    if (tid < 256) {
        float* rv = tv + tid * 16;
        unsigned short* rx = ti + tid * 16;
        int row = mb + (tid >> 1);
        int l   = blockIdx.y * 2 + (tid & 1);      // 8 lists per row
        size_t base = ((size_t)l * B_N + row) * KMAX;
        #pragma unroll
        for (int s = 0; s < 16; s++) {
            g_topv[base + s] = rv[s];
            g_topi[base + s] = colbase + (int)rx[s];
        }
    }
}

// ---------------- K3b: approx-top-32 prefilter + exact fp32 re-rank ----------
// one warp per row. Pool lists cover DISJOINT column ranges -> unique indices.
__global__ __launch_bounds__(256) void k_exact(const float* __restrict__ x) {
    int lane = threadIdx.x & 31;
    int row  = (blockIdx.x * 256 + threadIdx.x) >> 5;

    // ---- stage 1: load 128 approx (key, idx) pairs; select top-32 ----
    float akey[4]; int aidx[4];
    #pragma unroll
    for (int j = 0; j < 4; j++) {
        int p = lane * 4 + j;
        size_t off = ((size_t)(p >> 4) * B_N + row) * KMAX + (p & 15);
        akey[j] = g_topv[off];
        aidx[j] = g_topi[off];
    }
    int sel = 0;                       // lane s keeps the s-th selected idx
    #pragma unroll 1
    for (int s = 0; s < 32; s++) {
        float bk = akey[0]; int bi = aidx[0];
        #pragma unroll
        for (int j = 1; j < 4; j++)
            if (akey[j] > bk || (akey[j] == bk && aidx[j] < bi)) {
                bk = akey[j]; bi = aidx[j];
            }
        #pragma unroll
        for (int o = 16; o; o >>= 1) {
            float ok = __shfl_xor_sync(0xffffffffu, bk, o);
            int   oi = __shfl_xor_sync(0xffffffffu, bi, o);
            if (ok > bk || (ok == bk && oi < bi)) { bk = ok; bi = oi; }
        }
        if (lane == s) sel = bi;
        #pragma unroll
        for (int j = 0; j < 4; j++)
            if (aidx[j] == bi) akey[j] = -FLT_MAX;
    }

    // ---- stage 2: exact fp32 keys for the 32 survivors ----
    const float4* xr4 = (const float4*)(x + (size_t)row * D_N);
    float4 xa[3];
    #pragma unroll
    for (int t2 = 0; t2 < 3; t2++) xa[t2] = xr4[lane + 32 * t2];

    float ekey = -FLT_MAX;
    #pragma unroll 1
    for (int grp = 0; grp < 8; grp++) {
        int c[4];
        #pragma unroll
        for (int j = 0; j < 4; j++)
            c[j] = __shfl_sync(0xffffffffu, sel, grp * 4 + j);
        float d[4] = {0.f, 0.f, 0.f, 0.f};
        #pragma unroll
        for (int j = 0; j < 4; j++) {
            const float4* xc = (const float4*)(x + (size_t)c[j] * D_N);
            #pragma unroll
            for (int t2 = 0; t2 < 3; t2++) {
                float4 v = xc[lane + 32 * t2];
                d[j] = fmaf(xa[t2].x, v.x, d[j]);
                d[j] = fmaf(xa[t2].y, v.y, d[j]);
                d[j] = fmaf(xa[t2].z, v.z, d[j]);
                d[j] = fmaf(xa[t2].w, v.w, d[j]);
            }
        }
        #pragma unroll
        for (int o = 16; o; o >>= 1) {
            #pragma unroll
            for (int j = 0; j < 4; j++)
                d[j] += __shfl_xor_sync(0xffffffffu, d[j], o);
        }
        #pragma unroll
        for (int j = 0; j < 4; j++) {
            float kj = fmaf(2.f, d[j], -g_sq[c[j]]);
            if (lane == grp * 4 + j) ekey = kj;
        }
    }

    // ---- stage 3: exact top-16 by (key desc, idx asc) over 32 lanes ----
    int* out = g_idx + (size_t)row * KMAX;
    float ck = ekey; int ci = sel;
    #pragma unroll 1
    for (int s = 0; s < KMAX; s++) {
        float bk = ck; int bi = ci;
        #pragma unroll
        for (int o = 16; o; o >>= 1) {
            float ok = __shfl_xor_sync(0xffffffffu, bk, o);
            int   oi = __shfl_xor_sync(0xffffffffu, bi, o);
            if (ok > bk || (ok == bk && oi < bi)) { bk = ok; bi = oi; }
        }
        if (lane == 0) out[s] = bi;
        if (ci == bi) ck = -FLT_MAX;
    }
}

// ---------------- K4: gather-mean -> W_res -> relu -> +h -> LN -> fc ---------
__global__ __launch_bounds__(256) void k_tail(const float* __restrict__ Wres,
                                              const float* __restrict__ bres,
                                              const float* __restrict__ lng,
                                              const float* __restrict__ lnb,
                                              const float* __restrict__ Wfc,
                                              const float* __restrict__ bfc,
                                              float* __restrict__ out) {
    extern __shared__ float sm[];
    float* agg  = sm;
    float* hs   = agg + 16 * H_N;
    float* Ws   = hs + 16 * H_N;
    int*   idxs = (int*)(Ws + 32 * H_N);
    int*   ks   = idxs + 16 * 16;

    int tid = threadIdx.x;
    int rb = blockIdx.x * 16;
    {
        int r = tid >> 4, j = tid & 15;
        idxs[tid] = g_idx[(size_t)(rb + r) * KMAX + j];
    }
    if (tid < 16) ks[tid] = g_k[rb + tid];
    __syncthreads();

    int c = tid;
    for (int r = 0; r < 16; r++) {
        int kr = ks[r];
        float s = 0.f;
        for (int j = 0; j < kr; j++)
            s += g_h[(size_t)idxs[r * 16 + j] * H_N + c];
        agg[r * H_N + c] = s / (float)kr;
        hs[r * H_N + c]  = g_h[(size_t)(rb + r) * H_N + c];
    }
    __syncthreads();

    float acc[16];
    #pragma unroll
    for (int r = 0; r < 16; r++) acc[r] = 0.f;
    for (int kb = 0; kb < H_N; kb += 32) {
        __syncthreads();
        for (int kk = 0; kk < 32; kk++)
            Ws[kk * H_N + c] = Wres[(size_t)(kb + kk) * H_N + c];
        __syncthreads();
        for (int kk = 0; kk < 32; kk++) {
            float w = Ws[kk * H_N + c];
            #pragma unroll
            for (int r = 0; r < 16; r++)
                acc[r] = fmaf(agg[r * H_N + kb + kk], w, acc[r]);
        }
    }
    __syncthreads();

    float brc = bres[c];
    for (int r = 0; r < 16; r++) {
        float rv = acc[r] + brc;
        rv = rv > 0.f ? rv : 0.f;
        agg[r * H_N + c] = hs[r * H_N + c] + rv;
    }
    __syncthreads();

    int lane = tid & 31, wid = tid >> 5;
    for (int rr = 0; rr < 2; rr++) {
        int r = wid * 2 + rr;
        int row = rb + r;
        float* z = agg + r * H_N;
        float s = 0.f;
        #pragma unroll
        for (int t = 0; t < 8; t++) s += z[lane + 32 * t];
        #pragma unroll
        for (int o = 16; o; o >>= 1) s += __shfl_xor_sync(0xffffffffu, s, o);
        float mu = s * (1.f / 256.f);
        float vs = 0.f;
        #pragma unroll
        for (int t = 0; t < 8; t++) {
            float d = z[lane + 32 * t] - mu;
            vs = fmaf(d, d, vs);
        }
        #pragma unroll
        for (int o = 16; o; o >>= 1) vs += __shfl_xor_sync(0xffffffffu, vs, o);
        float rstd = rsqrtf(vs * (1.f / 256.f) + 1e-5f);

        float vals[8];
        #pragma unroll
        for (int t = 0; t < 8; t++) {
            int col = lane + 32 * t;
            float zn = (z[col] - mu) * rstd;
            vals[t] = zn * lng[col] + lnb[col];
        }
        #pragma unroll
        for (int cc = 0; cc < C_N; cc++) {
            float p = 0.f;
            #pragma unroll
            for (int t = 0; t < 8; t++) {
                int col = lane + 32 * t;
                p = fmaf(vals[t], Wfc[(size_t)col * C_N + cc], p);
            }
            #pragma unroll
            for (int o = 16; o; o >>= 1) p += __shfl_xor_sync(0xffffffffu, p, o);
            if (lane == 0) out[(size_t)row * C_N + cc] = p + bfc[cc];
        }
    }
}

// ---------------- launch ------------------------------------------------------
extern "C" void kernel_launch(void* const* d_in, const int* in_sizes, int n_in,
                              void* d_out, int out_size) {
    const float* x  = (const float*)d_in[0];
    const float* Wp = (const float*)d_in[1];
    const float* bp = (const float*)d_in[2];
    const float* Wt = (const float*)d_in[3];
    const float* bt = (const float*)d_in[4];
    const float* Wr = (const float*)d_in[5];
    const float* br = (const float*)d_in[6];
    const float* lg = (const float*)d_in[7];
    const float* lb = (const float*)d_in[8];
    const float* Wf = (const float*)d_in[9];
    const float* bf = (const float*)d_in[10];
    float* out = (float*)d_out;

    const int SMEM_TAIL = (16 * 256 * 2 + 32 * 256 + 16 * 16 + 16) * 4;
    cudaFuncSetAttribute(k_tail, cudaFuncAttributeMaxDynamicSharedMemorySize, SMEM_TAIL);
    cudaFuncSetAttribute(k_nn,   cudaFuncAttributeMaxDynamicSharedMemorySize, NN_SMEM);

    k_cvt<<<B_N, D_N>>>(x);
    k_sqtau<<<B_N / 8, dim3(32, 8)>>>(x, Wt, bt);
    k_proj<<<dim3(H_N / 64, B_N / 64), 256>>>(x, Wp, bp);
    k_nn<<<dim3(B_N / 128, NPART), 512, NN_SMEM>>>();
    k_exact<<<B_N / 8, 256>>>(x);
    k_tail<<<B_N / 16, 256, SMEM_TAIL>>>(Wr, br, lg, lb, Wf, bf, out);
}

// round 17
// speedup vs baseline: 1.3543x; 1.0663x over previous
#include <cuda_runtime.h>
#include <cuda_bf16.h>
#include <cuda_fp8.h>
#include <math.h>
#include <float.h>
#include <stdint.h>

#define B_N 8192
#define D_N 384
#define H_N 256
#define C_N 6
#define KMAX 16
#define NPART 4            // column quarters; x2 nc sub-lists -> 8 lists/row

// ---------------- scratch (static device globals; no runtime alloc) ----------
__device__ float         g_sq[B_N];
__device__ int           g_k[B_N];
__device__ float         g_h[(size_t)B_N * H_N];
__device__ float         g_topv[8 * (size_t)B_N * KMAX];   // approx keys
__device__ int           g_topi[8 * (size_t)B_N * KMAX];   // candidate pool
__device__ int           g_idx[(size_t)B_N * KMAX];
__device__ unsigned char g_x8[(size_t)B_N * D_N];          // e4m3(x)

#define SWZ(o) ((o) ^ (((o) >> 3) & 0x70))

__device__ __forceinline__ uint32_t smem_addr_u32(const void* p) {
    uint32_t a;
    asm("{ .reg .u64 t; cvta.to.shared.u64 t, %1; cvt.u32.u64 %0, t; }"
        : "=r"(a) : "l"(p));
    return a;
}
__device__ __forceinline__ void cp16(uint32_t dst, const void* src) {
    asm volatile("cp.async.cg.shared.global [%0], [%1], 16;" :: "r"(dst), "l"(src));
}
__device__ __forceinline__ void cp_commit() {
    asm volatile("cp.async.commit_group;" ::: "memory");
}
__device__ __forceinline__ void ldsm4(uint32_t& r0, uint32_t& r1, uint32_t& r2,
                                     uint32_t& r3, uint32_t addr) {
    asm volatile("ldmatrix.sync.aligned.m8n8.x4.shared.b16 {%0,%1,%2,%3}, [%4];"
                 : "=r"(r0), "=r"(r1), "=r"(r2), "=r"(r3) : "r"(addr));
}
// fp8 e4m3 MMA, K=32 per instruction; fragment bytes identical to bf16 k16 path
__device__ __forceinline__ void mma16832(float* c, const uint32_t* a,
                                         uint32_t b0, uint32_t b1) {
    asm volatile("mma.sync.aligned.m16n8k32.row.col.f32.e4m3.e4m3.f32 "
                 "{%0,%1,%2,%3}, {%4,%5,%6,%7}, {%8,%9}, {%0,%1,%2,%3};"
                 : "+f"(c[0]), "+f"(c[1]), "+f"(c[2]), "+f"(c[3])
                 : "r"(a[0]), "r"(a[1]), "r"(a[2]), "r"(a[3]),
                   "r"(b0), "r"(b1));
}
__device__ __forceinline__ void ins16(float* rv, unsigned short* rx, float kv,
                                      int col, float& cm) {
    int slot = 0;
    #pragma unroll
    for (int s = 1; s < 16; s++)
        if (rv[s] < rv[slot] || (rv[s] == rv[slot] && rx[s] > rx[slot])) slot = s;
    rv[slot] = kv; rx[slot] = (unsigned short)col;
    float nm = rv[0];
    #pragma unroll
    for (int s = 1; s < 16; s++) nm = fminf(nm, rv[s]);
    cm = nm;
}

// ---------------- K0: x -> e4m3 ----------------------------------------------
__global__ void k_cvt(const float* __restrict__ x) {
    int row = blockIdx.x;
    int k   = threadIdx.x;                     // 384 threads
    float v = x[(size_t)row * D_N + k];
    g_x8[(size_t)row * D_N + k] =
        __nv_cvt_float_to_fp8(v, __NV_SATFINITE, __NV_E4M3);
}

// ---------------- K1: sq[i] = ||x_i||^2 ; tau -> k ---------------------------
__global__ void k_sqtau(const float* __restrict__ x,
                        const float* __restrict__ Wtau,
                        const float* __restrict__ btau) {
    int row  = blockIdx.x * 8 + threadIdx.y;
    int lane = threadIdx.x;
    const float* xr = x + (size_t)row * D_N;
    float s = 0.f, t = 0.f;
    for (int i = lane; i < D_N; i += 32) {
        float v = xr[i];
        s = fmaf(v, v, s);
        t = fmaf(v, Wtau[i], t);
    }
    #pragma unroll
    for (int o = 16; o; o >>= 1) {
        s += __shfl_down_sync(0xffffffffu, s, o);
        t += __shfl_down_sync(0xffffffffu, t, o);
    }
    if (lane == 0) {
        g_sq[row] = s;
        float tau = 1.f / (1.f + expf(-(t + btau[0])));
        float kf  = rintf(16.f - 12.f * tau);
        kf = fminf(fmaxf(kf, 1.f), 16.f);
        g_k[row] = (int)kf;
    }
}

// ---------------- K2: h = relu(x @ W_proj + b_proj) --------------------------
__global__ __launch_bounds__(256) void k_proj(const float* __restrict__ x,
                                              const float* __restrict__ W,
                                              const float* __restrict__ bias) {
    __shared__ float As[16][68];
    __shared__ float Bs[16][68];
    int tid = threadIdx.x, tx = tid & 15, ty = tid >> 4;
    int mb = blockIdx.y * 64, nb = blockIdx.x * 64;
    float acc[4][4] = {};
    for (int kb = 0; kb < D_N; kb += 16) {
        {
            int r = tid >> 2, kq = (tid & 3) * 4;
            float4 va = *(const float4*)(x + (size_t)(mb + r) * D_N + kb + kq);
            As[kq + 0][r] = va.x; As[kq + 1][r] = va.y;
            As[kq + 2][r] = va.z; As[kq + 3][r] = va.w;
        }
        {
            int kr = tid >> 4, c = (tid & 15) * 4;
            float4 vb = *(const float4*)(W + (size_t)(kb + kr) * H_N + nb + c);
            *(float4*)&Bs[kr][c] = vb;
        }
        __syncthreads();
        #pragma unroll
        for (int k = 0; k < 16; k++) {
            float a[4], bv[4];
            #pragma unroll
            for (int i = 0; i < 4; i++) a[i] = As[k][ty * 4 + i];
            #pragma unroll
            for (int j = 0; j < 4; j++) bv[j] = Bs[k][tx * 4 + j];
            #pragma unroll
            for (int i = 0; i < 4; i++)
                #pragma unroll
                for (int j = 0; j < 4; j++)
                    acc[i][j] = fmaf(a[i], bv[j], acc[i][j]);
        }
        __syncthreads();
    }
    #pragma unroll
    for (int i = 0; i < 4; i++) {
        int row = mb + ty * 4 + i;
        #pragma unroll
        for (int j = 0; j < 4; j++) {
            int col = nb + tx * 4 + j;
            float v = acc[i][j] + bias[col];
            g_h[(size_t)row * H_N + col] = v > 0.f ? v : 0.f;
        }
    }
}

// ---------------- K3: e4m3 HMMA filter, unified 96-slab stream ---------------
// grid (64 row-tiles, 4 col-quarters); 512 threads (8x2 warp grid); 2 CTA/SM
// slab = K=128 fp8 bytes: A 128x128B = 16KB, B 64x128B = 8KB; 3 slabs/tile
#define NN_STAGE    24576
#define NN_BOFF     16384
#define NN_TV_OFF   (3 * NN_STAGE)                   // 73728
#define NN_TI_OFF   (NN_TV_OFF + 256 * 16 * 4)       // 90112
#define NN_TMIN_OFF (NN_TI_OFF + 256 * 16 * 2)       // 98304
#define NN_SQC_OFF  (NN_TMIN_OFF + 256 * 4)          // 99328
#define NN_SMEM     (NN_SQC_OFF + 2 * 64 * 4)        // 99840
#define NN_TILES    (2048 / 64)      // 32 col tiles per quarter
#define NN_SLABS    3                // 384 fp8 bytes / 128
#define NN_GTOT     (NN_TILES * NN_SLABS)            // 96

__device__ __forceinline__ void load_slab(uint32_t smem_u32, int stage,
                                          int mb, int cb, int t, int tid) {
    uint32_t sbase = smem_u32 + stage * NN_STAGE;
    // A: 128 rows x 128B = 1024 chunks of 16B; 2 per thread
    #pragma unroll
    for (int i = 0; i < 2; i++) {
        int c = tid + i * 512;
        int row = c >> 3, j = c & 7;
        uint32_t dst = SWZ((uint32_t)(row * 128 + j * 16));
        cp16(sbase + dst, g_x8 + (size_t)(mb + row) * D_N + t * 128 + j * 16);
    }
    // B: 64 rows x 128B = 512 chunks; 1 per thread
    {
        int c = tid;
        int row = c >> 3, j = c & 7;
        uint32_t dst = SWZ((uint32_t)(row * 128 + j * 16));
        cp16(sbase + NN_BOFF + dst, g_x8 + (size_t)(cb + row) * D_N + t * 128 + j * 16);
    }
    cp_commit();
}

__global__ __launch_bounds__(512, 2) void k_nn() {
    extern __shared__ __align__(1024) char smem[];
    uint32_t smem_u32 = smem_addr_u32(smem);
    float*          tv   = (float*)(smem + NN_TV_OFF);    // 256 lists x 16
    unsigned short* ti   = (unsigned short*)(smem + NN_TI_OFF);
    float*          tmin = (float*)(smem + NN_TMIN_OFF);  // 256
    float*          sqc  = (float*)(smem + NN_SQC_OFF);   // [2][64]

    int tid = threadIdx.x, lane = tid & 31, wid = tid >> 5;
    int mr = wid >> 1, nc = wid & 1;      // warp grid 8x2
    int mb = blockIdx.x * 128;
    int colbase = blockIdx.y * 2048;

    for (int i = tid; i < 256 * 16; i += 512) { tv[i] = -FLT_MAX; ti[i] = 0xFFFF; }
    if (tid < 256) tmin[tid] = -FLT_MAX;

    int lrow = lane & 15, lkoff = (lane >> 4) * 16;
    int q4 = lane & 3;
    int r0 = mr * 16 + (lane >> 2);
    int r1 = r0 + 8;
    int l0 = r0 * 2 + nc, l1 = r1 * 2 + nc;

    // prologue: global slabs 0,1 (tile 0 slabs 0,1) + sq tile 0
    load_slab(smem_u32, 0, mb, colbase, 0, tid);
    load_slab(smem_u32, 1, mb, colbase, 1, tid);
    if (tid < 64) sqc[tid] = g_sq[colbase + tid];

    float acc[4][4];
    #pragma unroll
    for (int ni = 0; ni < 4; ni++)
        #pragma unroll
        for (int q = 0; q < 4; q++) acc[ni][q] = 0.f;

    int ct = 0, sidx = 0;
    #pragma unroll 1
    for (int g = 0; g < NN_GTOT; g++) {
        if (g == NN_GTOT - 1)
            asm volatile("cp.async.wait_group 0;" ::: "memory");
        else
            asm volatile("cp.async.wait_group 1;" ::: "memory");
        __syncthreads();

        // issue slab g+2 (crosses tile boundaries — no drain between tiles)
        if (g + 2 < NN_GTOT) {
            int gn = g + 2;
            int tn = gn / NN_SLABS, sn = gn - tn * NN_SLABS;
            load_slab(smem_u32, gn % 3, mb, colbase + tn * 64, sn, tid);
        }
        // prefetch next tile's sq mid-tile (>=2 barriers after prior epilogue read)
        if (sidx == 1 && ct + 1 < NN_TILES && tid < 64)
            sqc[((ct + 1) & 1) * 64 + tid] = g_sq[colbase + (ct + 1) * 64 + tid];

        uint32_t sbase = smem_u32 + (g % 3) * NN_STAGE;
        uint32_t aBase = sbase;
        uint32_t bBase = sbase + NN_BOFF;

        // 128 fp8-k per slab = 4 k32 MMA steps; byte offsets same as bf16 path
        #pragma unroll
        for (int kk = 0; kk < 4; kk++) {
            uint32_t af[4];
            {
                int row = mr * 16 + lrow;
                uint32_t off = SWZ((uint32_t)(row * 128 + kk * 32 + lkoff));
                ldsm4(af[0], af[1], af[2], af[3], aBase + off);
            }
            #pragma unroll
            for (int bi = 0; bi < 2; bi++) {
                int row = nc * 32 + bi * 16 + lrow;
                uint32_t off = SWZ((uint32_t)(row * 128 + kk * 32 + lkoff));
                uint32_t b0, b1, b2, b3;
                ldsm4(b0, b1, b2, b3, bBase + off);
                mma16832(acc[bi * 2 + 0], af, b0, b2);
                mma16832(acc[bi * 2 + 1], af, b1, b3);
            }
        }

        if (sidx == NN_SLABS - 1) {
            // ---- epilogue for tile ct: approx keys + rare inserts ----
            const float* sqp = sqc + (ct & 1) * 64;
            float m0 = tmin[l0], m1 = tmin[l1];
            bool hit = false;
            #pragma unroll
            for (int ni = 0; ni < 4; ni++) {
                int c0 = nc * 32 + ni * 8 + 2 * q4;
                float s0 = sqp[c0], s1 = sqp[c0 + 1];
                float k0 = fmaf(2.f, acc[ni][0], -s0);
                float k1 = fmaf(2.f, acc[ni][1], -s1);
                float k2 = fmaf(2.f, acc[ni][2], -s0);
                float k3 = fmaf(2.f, acc[ni][3], -s1);
                hit |= (k0 > m0) | (k1 > m0) | (k2 > m1) | (k3 > m1);
            }
            unsigned mask = __ballot_sync(0xffffffffu, hit);
            if (mask) {
                #pragma unroll 1
                for (int phase = 0; phase < 4; phase++) {
                    if (q4 == phase && hit) {
                        float cm0 = tmin[l0], cm1 = tmin[l1];
                        float* rv0 = tv + l0 * 16; unsigned short* rx0 = ti + l0 * 16;
                        float* rv1 = tv + l1 * 16; unsigned short* rx1 = ti + l1 * 16;
                        #pragma unroll 1
                        for (int ni = 0; ni < 4; ni++) {
                            int cl = nc * 32 + ni * 8 + 2 * q4;
                            float s0 = sqp[cl], s1 = sqp[cl + 1];
                            float k0 = fmaf(2.f, acc[ni][0], -s0);
                            float k1 = fmaf(2.f, acc[ni][1], -s1);
                            float k2 = fmaf(2.f, acc[ni][2], -s0);
                            float k3 = fmaf(2.f, acc[ni][3], -s1);
                            int c0 = ct * 64 + cl;
                            if (k0 > cm0) ins16(rv0, rx0, k0, c0, cm0);
                            if (k1 > cm0) ins16(rv0, rx0, k1, c0 + 1, cm0);
                            if (k2 > cm1) ins16(rv1, rx1, k2, c0, cm1);
                            if (k3 > cm1) ins16(rv1, rx1, k3, c0 + 1, cm1);
                        }
                        tmin[l0] = cm0; tmin[l1] = cm1;
                    }
                    __syncwarp();
                }
            }
            #pragma unroll
            for (int ni = 0; ni < 4; ni++)
                #pragma unroll
                for (int q = 0; q < 4; q++) acc[ni][q] = 0.f;
            ct++; sidx = 0;
        } else {
            sidx++;
        }
    }

    __syncthreads();

    // ---- dump candidate pool + approx keys ----
    if (tid < 256) {
        float* rv = tv + tid * 16;
        unsigned short* rx = ti + tid * 16;
        int row = mb + (tid >> 1);
        int l   = blockIdx.y * 2 + (tid & 1);      // 8 lists per row
        size_t base = ((size_t)l * B_N + row) * KMAX;
        #pragma unroll
        for (int s = 0; s < 16; s++) {
            g_topv[base + s] = rv[s];
            g_topi[base + s] = colbase + (int)rx[s];
        }
    }
}

// ---------------- K3b: approx-top-32 prefilter + exact fp32 re-rank ----------
// one warp per row. Pool lists cover DISJOINT column ranges -> unique indices.
__global__ __launch_bounds__(256) void k_exact(const float* __restrict__ x) {
    int lane = threadIdx.x & 31;
    int row  = (blockIdx.x * 256 + threadIdx.x) >> 5;

    // ---- stage 1: load 128 approx (key, idx) pairs; select top-32 ----
    float akey[4]; int aidx[4];
    #pragma unroll
    for (int j = 0; j < 4; j++) {
        int p = lane * 4 + j;
        size_t off = ((size_t)(p >> 4) * B_N + row) * KMAX + (p & 15);
        akey[j] = g_topv[off];
        aidx[j] = g_topi[off];
    }
    int sel = 0;                       // lane s keeps the s-th selected idx
    #pragma unroll 1
    for (int s = 0; s < 32; s++) {
        float bk = akey[0]; int bi = aidx[0];
        #pragma unroll
        for (int j = 1; j < 4; j++)
            if (akey[j] > bk || (akey[j] == bk && aidx[j] < bi)) {
                bk = akey[j]; bi = aidx[j];
            }
        #pragma unroll
        for (int o = 16; o; o >>= 1) {
            float ok = __shfl_xor_sync(0xffffffffu, bk, o);
            int   oi = __shfl_xor_sync(0xffffffffu, bi, o);
            if (ok > bk || (ok == bk && oi < bi)) { bk = ok; bi = oi; }
        }
        if (lane == s) sel = bi;
        #pragma unroll
        for (int j = 0; j < 4; j++)
            if (aidx[j] == bi) akey[j] = -FLT_MAX;
    }

    // ---- stage 2: exact fp32 keys for the 32 survivors ----
    const float4* xr4 = (const float4*)(x + (size_t)row * D_N);
    float4 xa[3];
    #pragma unroll
    for (int t2 = 0; t2 < 3; t2++) xa[t2] = xr4[lane + 32 * t2];

    float ekey = -FLT_MAX;
    #pragma unroll 1
    for (int grp = 0; grp < 8; grp++) {
        int c[4];
        #pragma unroll
        for (int j = 0; j < 4; j++)
            c[j] = __shfl_sync(0xffffffffu, sel, grp * 4 + j);
        float d[4] = {0.f, 0.f, 0.f, 0.f};
        #pragma unroll
        for (int j = 0; j < 4; j++) {
            const float4* xc = (const float4*)(x + (size_t)c[j] * D_N);
            #pragma unroll
            for (int t2 = 0; t2 < 3; t2++) {
                float4 v = xc[lane + 32 * t2];
                d[j] = fmaf(xa[t2].x, v.x, d[j]);
                d[j] = fmaf(xa[t2].y, v.y, d[j]);
                d[j] = fmaf(xa[t2].z, v.z, d[j]);
                d[j] = fmaf(xa[t2].w, v.w, d[j]);
            }
        }
        #pragma unroll
        for (int o = 16; o; o >>= 1) {
            #pragma unroll
            for (int j = 0; j < 4; j++)
                d[j] += __shfl_xor_sync(0xffffffffu, d[j], o);
        }
        #pragma unroll
        for (int j = 0; j < 4; j++) {
            float kj = fmaf(2.f, d[j], -g_sq[c[j]]);
            if (lane == grp * 4 + j) ekey = kj;
        }
    }

    // ---- stage 3: exact top-16 by (key desc, idx asc) over 32 lanes ----
    int* out = g_idx + (size_t)row * KMAX;
    float ck = ekey; int ci = sel;
    #pragma unroll 1
    for (int s = 0; s < KMAX; s++) {
        float bk = ck; int bi = ci;
        #pragma unroll
        for (int o = 16; o; o >>= 1) {
            float ok = __shfl_xor_sync(0xffffffffu, bk, o);
            int   oi = __shfl_xor_sync(0xffffffffu, bi, o);
            if (ok > bk || (ok == bk && oi < bi)) { bk = ok; bi = oi; }
        }
        if (lane == 0) out[s] = bi;
        if (ci == bi) ck = -FLT_MAX;
    }
}

// ---------------- K4: gather-mean -> W_res -> relu -> +h -> LN -> fc ---------
__global__ __launch_bounds__(256) void k_tail(const float* __restrict__ Wres,
                                              const float* __restrict__ bres,
                                              const float* __restrict__ lng,
                                              const float* __restrict__ lnb,
                                              const float* __restrict__ Wfc,
                                              const float* __restrict__ bfc,
                                              float* __restrict__ out) {
    extern __shared__ float sm[];
    float* agg  = sm;
    float* hs   = agg + 16 * H_N;
    float* Ws   = hs + 16 * H_N;
    int*   idxs = (int*)(Ws + 32 * H_N);
    int*   ks   = idxs + 16 * 16;

    int tid = threadIdx.x;
    int rb = blockIdx.x * 16;
    {
        int r = tid >> 4, j = tid & 15;
        idxs[tid] = g_idx[(size_t)(rb + r) * KMAX + j];
    }
    if (tid < 16) ks[tid] = g_k[rb + tid];
    __syncthreads();

    int c = tid;
    for (int r = 0; r < 16; r++) {
        int kr = ks[r];
        float s = 0.f;
        for (int j = 0; j < kr; j++)
            s += g_h[(size_t)idxs[r * 16 + j] * H_N + c];
        agg[r * H_N + c] = s / (float)kr;
        hs[r * H_N + c]  = g_h[(size_t)(rb + r) * H_N + c];
    }
    __syncthreads();

    float acc[16];
    #pragma unroll
    for (int r = 0; r < 16; r++) acc[r] = 0.f;
    for (int kb = 0; kb < H_N; kb += 32) {
        __syncthreads();
        for (int kk = 0; kk < 32; kk++)
            Ws[kk * H_N + c] = Wres[(size_t)(kb + kk) * H_N + c];
        __syncthreads();
        for (int kk = 0; kk < 32; kk++) {
            float w = Ws[kk * H_N + c];
            #pragma unroll
            for (int r = 0; r < 16; r++)
                acc[r] = fmaf(agg[r * H_N + kb + kk], w, acc[r]);
        }
    }
    __syncthreads();

    float brc = bres[c];
    for (int r = 0; r < 16; r++) {
        float rv = acc[r] + brc;
        rv = rv > 0.f ? rv : 0.f;
        agg[r * H_N + c] = hs[r * H_N + c] + rv;
    }
    __syncthreads();

    int lane = tid & 31, wid = tid >> 5;
    for (int rr = 0; rr < 2; rr++) {
        int r = wid * 2 + rr;
        int row = rb + r;
        float* z = agg + r * H_N;
        float s = 0.f;
        #pragma unroll
        for (int t = 0; t < 8; t++) s += z[lane + 32 * t];
        #pragma unroll
        for (int o = 16; o; o >>= 1) s += __shfl_xor_sync(0xffffffffu, s, o);
        float mu = s * (1.f / 256.f);
        float vs = 0.f;
        #pragma unroll
        for (int t = 0; t < 8; t++) {
            float d = z[lane + 32 * t] - mu;
            vs = fmaf(d, d, vs);
        }
        #pragma unroll
        for (int o = 16; o; o >>= 1) vs += __shfl_xor_sync(0xffffffffu, vs, o);
        float rstd = rsqrtf(vs * (1.f / 256.f) + 1e-5f);

        float vals[8];
        #pragma unroll
        for (int t = 0; t < 8; t++) {
            int col = lane + 32 * t;
            float zn = (z[col] - mu) * rstd;
            vals[t] = zn * lng[col] + lnb[col];
        }
        #pragma unroll
        for (int cc = 0; cc < C_N; cc++) {
            float p = 0.f;
            #pragma unroll
            for (int t = 0; t < 8; t++) {
                int col = lane + 32 * t;
                p = fmaf(vals[t], Wfc[(size_t)col * C_N + cc], p);
            }
            #pragma unroll
            for (int o = 16; o; o >>= 1) p += __shfl_xor_sync(0xffffffffu, p, o);
            if (lane == 0) out[(size_t)row * C_N + cc] = p + bfc[cc];
        }
    }
}

// ---------------- launch ------------------------------------------------------
extern "C" void kernel_launch(void* const* d_in, const int* in_sizes, int n_in,
                              void* d_out, int out_size) {
    const float* x  = (const float*)d_in[0];
    const float* Wp = (const float*)d_in[1];
    const float* bp = (const float*)d_in[2];
    const float* Wt = (const float*)d_in[3];
    const float* bt = (const float*)d_in[4];
    const float* Wr = (const float*)d_in[5];
    const float* br = (const float*)d_in[6];
    const float* lg = (const float*)d_in[7];
    const float* lb = (const float*)d_in[8];
    const float* Wf = (const float*)d_in[9];
    const float* bf = (const float*)d_in[10];
    float* out = (float*)d_out;

    const int SMEM_TAIL = (16 * 256 * 2 + 32 * 256 + 16 * 16 + 16) * 4;
    cudaFuncSetAttribute(k_tail, cudaFuncAttributeMaxDynamicSharedMemorySize, SMEM_TAIL);
    cudaFuncSetAttribute(k_nn,   cudaFuncAttributeMaxDynamicSharedMemorySize, NN_SMEM);

    k_cvt<<<B_N, D_N>>>(x);
    k_sqtau<<<B_N / 8, dim3(32, 8)>>>(x, Wt, bt);
    k_proj<<<dim3(H_N / 64, B_N / 64), 256>>>(x, Wp, bp);
    k_nn<<<dim3(B_N / 128, NPART), 512, NN_SMEM>>>();
    k_exact<<<B_N / 8, 256>>>(x);
    k_tail<<<B_N / 16, 256, SMEM_TAIL>>>(Wr, br, lg, lb, Wf, bf, out);
}